// round 1
// baseline (speedup 1.0000x reference)
#include <cuda_runtime.h>

#define BB   8
#define SS   512
#define HH   16
#define DD   64
#define HIDN 1024
#define BH   (BB*HH)   // 128

// ---------------- scratch (device globals: allocation-free) ----------------
__device__ float g_q[BH*SS*DD];                 // [b,h,s,d] 16MB
__device__ float g_k[BH*SS*DD];
__device__ float g_v[BH*SS*DD];
__device__ float g_pos[HH*1024*DD];             // [h,p,d]   4MB
__device__ float g_scores[(size_t)BH*SS*SS];    // [bh,i,j]  128MB
__device__ float g_m[BH*SS];
__device__ float g_l[BH*SS];

// ---------------- projection GEMM: C = X @ W^T + b, scattered -------------
// 128x128 tile, 256 threads, 8x8 microtile, K-chunk 16.
__global__ __launch_bounds__(256) void gemm_proj(
    const float* __restrict__ X, const float* __restrict__ W,
    const float* __restrict__ bias, int mode, int which)
{
    __shared__ float As[16][132];
    __shared__ float Bs[16][132];
    const int bm = blockIdx.y * 128;
    const int bn = blockIdx.x * 128;
    const int tid = threadIdx.x;
    const int tx = tid & 15, ty = tid >> 4;
    const int lr = tid >> 2;          // 0..63
    const int lc = (tid & 3) << 2;    // 0,4,8,12

    float acc[8][8];
#pragma unroll
    for (int u = 0; u < 8; u++)
#pragma unroll
        for (int v = 0; v < 8; v++) acc[u][v] = 0.f;

    const float* Arow0 = X + (size_t)(bm + lr) * HIDN + lc;
    const float* Arow1 = Arow0 + (size_t)64 * HIDN;
    const float* Brow0 = W + (size_t)(bn + lr) * HIDN + lc;
    const float* Brow1 = Brow0 + (size_t)64 * HIDN;

    for (int kc = 0; kc < HIDN; kc += 16) {
        float4 a0 = *(const float4*)(Arow0 + kc);
        float4 a1 = *(const float4*)(Arow1 + kc);
        float4 b0 = *(const float4*)(Brow0 + kc);
        float4 b1 = *(const float4*)(Brow1 + kc);
        __syncthreads();
        As[lc+0][lr]    = a0.x; As[lc+1][lr]    = a0.y; As[lc+2][lr]    = a0.z; As[lc+3][lr]    = a0.w;
        As[lc+0][lr+64] = a1.x; As[lc+1][lr+64] = a1.y; As[lc+2][lr+64] = a1.z; As[lc+3][lr+64] = a1.w;
        Bs[lc+0][lr]    = b0.x; Bs[lc+1][lr]    = b0.y; Bs[lc+2][lr]    = b0.z; Bs[lc+3][lr]    = b0.w;
        Bs[lc+0][lr+64] = b1.x; Bs[lc+1][lr+64] = b1.y; Bs[lc+2][lr+64] = b1.z; Bs[lc+3][lr+64] = b1.w;
        __syncthreads();
#pragma unroll
        for (int t = 0; t < 16; t++) {
            float af[8], bf[8];
            *(float4*)&af[0] = *(const float4*)&As[t][ty*8];
            *(float4*)&af[4] = *(const float4*)&As[t][ty*8+4];
            *(float4*)&bf[0] = *(const float4*)&Bs[t][tx*8];
            *(float4*)&bf[4] = *(const float4*)&Bs[t][tx*8+4];
#pragma unroll
            for (int u = 0; u < 8; u++)
#pragma unroll
                for (int v = 0; v < 8; v++)
                    acc[u][v] += af[u] * bf[v];
        }
    }

    float* outp = (which == 0) ? g_q : (which == 1) ? g_k : (which == 2) ? g_v : g_pos;
#pragma unroll
    for (int u = 0; u < 8; u++) {
        const int m = bm + ty*8 + u;
#pragma unroll
        for (int v = 0; v < 8; v++) {
            const int n = bn + tx*8 + v;
            const float val = acc[u][v] + bias[n];
            size_t oi;
            if (mode == 0) {  // q/k/v: m = b*512+s, n = h*64+d -> [b,h,s,d]
                const int b = m >> 9, s = m & 511, h = n >> 6, d = n & 63;
                oi = (((size_t)(b*HH + h))*SS + s)*DD + d;
            } else {          // pos: m = p, n = h*64+d -> [h,p,d]
                oi = (((size_t)(n >> 6))*1024 + m)*DD + (n & 63);
            }
            outp[oi] = val;
        }
    }
}

// ---------------- fused disentangled score kernel --------------------------
// score[i,j] = (q_i.k_j + pos_idx.k_j)/sqrt(48) + (q_i.pos_idx)/sqrt(3072) + mask[b,j]
// idx = clip(i-j+512, 0, 1023). Block computes a 64x64 (i,j) tile; only 127
// pos rows are touched (anti-diagonals).
__global__ __launch_bounds__(256) void score_kernel(const float* __restrict__ mask)
{
    __shared__ float qs[64][33];
    __shared__ float ks[64][33];
    __shared__ float ps[127][33];
    const int j0 = blockIdx.x * 64;
    const int i0 = blockIdx.y * 64;
    const int bh = blockIdx.z;
    const int b = bh >> 4, h = bh & 15;
    const int tid = threadIdx.x;
    const int tx = tid & 15, ty = tid >> 4;

    const float* qptr = g_q + ((size_t)bh*SS + i0) * DD;
    const float* kptr = g_k + ((size_t)bh*SS + j0) * DD;
    const float* pptr = g_pos + (size_t)h * 1024 * DD;
    const int base = i0 - j0 + 449;           // lowest pos row touched by tile

    float cc[4][4], cp[4][4], pc[4][4];
#pragma unroll
    for (int a = 0; a < 4; a++)
#pragma unroll
        for (int c2 = 0; c2 < 4; c2++) { cc[a][c2] = 0.f; cp[a][c2] = 0.f; pc[a][c2] = 0.f; }

    const int pbase = (ty - tx) * 4 + 60;     // in [0,120]
    const int r = tid >> 3;                   // 0..31
    const int cq = (tid & 7) << 2;            // 0..28

    for (int dc = 0; dc < DD; dc += 32) {
        float4 qa  = *(const float4*)(qptr + (size_t)r      * DD + dc + cq);
        float4 qb  = *(const float4*)(qptr + (size_t)(r+32) * DD + dc + cq);
        float4 ka  = *(const float4*)(kptr + (size_t)r      * DD + dc + cq);
        float4 kb4 = *(const float4*)(kptr + (size_t)(r+32) * DD + dc + cq);
        __syncthreads();
        qs[r][cq+0]=qa.x;  qs[r][cq+1]=qa.y;  qs[r][cq+2]=qa.z;  qs[r][cq+3]=qa.w;
        qs[r+32][cq+0]=qb.x; qs[r+32][cq+1]=qb.y; qs[r+32][cq+2]=qb.z; qs[r+32][cq+3]=qb.w;
        ks[r][cq+0]=ka.x;  ks[r][cq+1]=ka.y;  ks[r][cq+2]=ka.z;  ks[r][cq+3]=ka.w;
        ks[r+32][cq+0]=kb4.x; ks[r+32][cq+1]=kb4.y; ks[r+32][cq+2]=kb4.z; ks[r+32][cq+3]=kb4.w;
        for (int u = tid; u < 127*8; u += 256) {
            const int pr = u >> 3;
            const int pcc = (u & 7) << 2;
            int grow = base + pr;
            grow = grow < 0 ? 0 : (grow > 1023 ? 1023 : grow);
            float4 pv4 = *(const float4*)(pptr + (size_t)grow * DD + dc + pcc);
            ps[pr][pcc+0]=pv4.x; ps[pr][pcc+1]=pv4.y; ps[pr][pcc+2]=pv4.z; ps[pr][pcc+3]=pv4.w;
        }
        __syncthreads();
#pragma unroll 4
        for (int d = 0; d < 32; d++) {
            float qv[4], kv[4], pv[7];
#pragma unroll
            for (int a = 0; a < 4; a++) qv[a] = qs[ty*4+a][d];
#pragma unroll
            for (int c2 = 0; c2 < 4; c2++) kv[c2] = ks[tx*4+c2][d];
#pragma unroll
            for (int u = 0; u < 7; u++) pv[u] = ps[pbase+u][d];
#pragma unroll
            for (int a = 0; a < 4; a++)
#pragma unroll
                for (int c2 = 0; c2 < 4; c2++) {
                    const float p = pv[a - c2 + 3];
                    cc[a][c2] += qv[a] * kv[c2];
                    cp[a][c2] += qv[a] * p;
                    pc[a][c2] += p * kv[c2];
                }
        }
    }

    const float s1 = 0.14433756729740643f;    // 1/sqrt(48)
    const float s2 = s1 * 0.125f;             // 1/sqrt(3072)
    float* sp = g_scores + ((size_t)bh*SS + i0)*SS + j0;
    const float* mrow = mask + (size_t)b*SS + j0;
#pragma unroll
    for (int a = 0; a < 4; a++)
#pragma unroll
        for (int c2 = 0; c2 < 4; c2++) {
            const int jj = tx*4 + c2;
            sp[(size_t)(ty*4+a)*SS + jj] =
                (cc[a][c2] + pc[a][c2]) * s1 + cp[a][c2] * s2 + mrow[jj];
        }
}

// ---------------- softmax stats: per-row max & sumexp ----------------------
__global__ __launch_bounds__(256) void stats_kernel()
{
    const int warp = threadIdx.x >> 5;
    const int lane = threadIdx.x & 31;
    const size_t row = (size_t)blockIdx.x * 8 + warp;
    const float* sp = g_scores + row * SS;
    float v[16];
    float m = -1e30f;
#pragma unroll
    for (int t = 0; t < 4; t++) {
        float4 x = *(const float4*)(sp + t*128 + lane*4);
        v[t*4+0]=x.x; v[t*4+1]=x.y; v[t*4+2]=x.z; v[t*4+3]=x.w;
        m = fmaxf(m, fmaxf(fmaxf(x.x, x.y), fmaxf(x.z, x.w)));
    }
#pragma unroll
    for (int o = 16; o; o >>= 1) m = fmaxf(m, __shfl_xor_sync(0xffffffffu, m, o));
    float l = 0.f;
#pragma unroll
    for (int t = 0; t < 16; t++) l += __expf(v[t] - m);
#pragma unroll
    for (int o = 16; o; o >>= 1) l += __shfl_xor_sync(0xffffffffu, l, o);
    if (lane == 0) { g_m[row] = m; g_l[row] = l; }
}

// ---------------- PV: out = softmax(scores) @ V ----------------------------
__global__ __launch_bounds__(256) void pv_kernel(float* __restrict__ out)
{
    __shared__ float psm[64][65];
    __shared__ float vs[64][65];
    __shared__ float mrow[64], lrow[64];
    const int i0 = blockIdx.y * 64;
    const int bh = blockIdx.z;
    const int b = bh >> 4, h = bh & 15;
    const int tid = threadIdx.x;
    const int tx = tid & 15, ty = tid >> 4;

    if (tid < 64) {
        mrow[tid] = g_m[(size_t)bh*SS + i0 + tid];
        lrow[tid] = 1.f / g_l[(size_t)bh*SS + i0 + tid];
    }
    __syncthreads();

    float acc[4][4];
#pragma unroll
    for (int a = 0; a < 4; a++)
#pragma unroll
        for (int c2 = 0; c2 < 4; c2++) acc[a][c2] = 0.f;

    const int r = tid >> 2;            // 0..63
    const int c = (tid & 3) << 4;      // 0,16,32,48
    const float m_r  = mrow[r];
    const float li_r = lrow[r];
    const float* srow = g_scores + ((size_t)bh*SS + i0 + r) * SS;

    for (int jc = 0; jc < SS; jc += 64) {
        __syncthreads();
#pragma unroll
        for (int u = 0; u < 16; u += 4) {
            float4 x = *(const float4*)(srow + jc + c + u);
            psm[r][c+u+0] = __expf(x.x - m_r) * li_r;
            psm[r][c+u+1] = __expf(x.y - m_r) * li_r;
            psm[r][c+u+2] = __expf(x.z - m_r) * li_r;
            psm[r][c+u+3] = __expf(x.w - m_r) * li_r;
        }
        const float* vrow = g_v + ((size_t)bh*SS + jc + r) * DD;
#pragma unroll
        for (int u = 0; u < 16; u += 4) {
            float4 x = *(const float4*)(vrow + c + u);
            vs[r][c+u+0]=x.x; vs[r][c+u+1]=x.y; vs[r][c+u+2]=x.z; vs[r][c+u+3]=x.w;
        }
        __syncthreads();
#pragma unroll 8
        for (int jj = 0; jj < 64; jj++) {
            float pf[4], vf[4];
#pragma unroll
            for (int a = 0; a < 4; a++) pf[a] = psm[ty*4+a][jj];
#pragma unroll
            for (int c2 = 0; c2 < 4; c2++) vf[c2] = vs[jj][tx*4+c2];
#pragma unroll
            for (int a = 0; a < 4; a++)
#pragma unroll
                for (int c2 = 0; c2 < 4; c2++) acc[a][c2] += pf[a] * vf[c2];
        }
    }

#pragma unroll
    for (int a = 0; a < 4; a++) {
        const int i = i0 + ty*4 + a;
#pragma unroll
        for (int c2 = 0; c2 < 4; c2++)
            out[((size_t)b*SS + i)*HIDN + h*DD + tx*4 + c2] = acc[a][c2];
    }
}

// ---------------- launch ---------------------------------------------------
extern "C" void kernel_launch(void* const* d_in, const int* in_sizes, int n_in,
                              void* d_out, int out_size)
{
    const float* hs  = (const float*)d_in[0];
    const float* msk = (const float*)d_in[1];
    // d_in[2] relative_pos: by construction rel[i,j] = i-j; computed in-kernel.
    const float* Wq  = (const float*)d_in[3];
    const float* bq  = (const float*)d_in[4];
    const float* Wk  = (const float*)d_in[5];
    const float* bk  = (const float*)d_in[6];
    const float* Wv  = (const float*)d_in[7];
    const float* bv  = (const float*)d_in[8];
    const float* Wpk = (const float*)d_in[9];
    const float* bpk = (const float*)d_in[10];
    const float* rel = (const float*)d_in[11];
    float* out = (float*)d_out;

    dim3 gq(HIDN/128, (BB*SS)/128);       // (8, 32)
    gemm_proj<<<gq, 256>>>(hs, Wq, bq, 0, 0);
    gemm_proj<<<gq, 256>>>(hs, Wk, bk, 0, 1);
    gemm_proj<<<gq, 256>>>(hs, Wv, bv, 0, 2);
    dim3 gp(HIDN/128, 1024/128);          // (8, 8)
    gemm_proj<<<gp, 256>>>(rel, Wpk, bpk, 1, 3);

    dim3 gs(SS/64, SS/64, BH);            // (8, 8, 128)
    score_kernel<<<gs, 256>>>(msk);

    stats_kernel<<<BH*SS/8, 256>>>();

    dim3 gpv(1, SS/64, BH);               // (1, 8, 128)
    pv_kernel<<<gpv, 256>>>(out);
}

// round 3
// speedup vs baseline: 1.5258x; 1.5258x over previous
#include <cuda_runtime.h>
#include <cstdint>

#define BB   8
#define SS   512
#define HH   16
#define DD   64
#define HIDN 1024
#define BH   (BB*HH)   // 128

// ---------------- scratch (device globals: allocation-free) ----------------
__device__ float g_q[BH*SS*DD];                 // [b,h,s,d] 16MB
__device__ float g_k[BH*SS*DD];
__device__ float g_v[BH*SS*DD];
__device__ float g_pos[HH*1024*DD];             // [h,p,d]   4MB
__device__ float g_scores[(size_t)BH*SS*SS];    // [bh,i,j]  128MB
__device__ float g_m[BH*SS];
__device__ float g_l[BH*SS];

// ---------------- helpers ---------------------------------------------------
__device__ __forceinline__ uint32_t f2tf(float f) {
    uint32_t u;
    asm("cvt.rna.tf32.f32 %0, %1;" : "=r"(u) : "f"(f));
    return u;
}
__device__ __forceinline__ void mma_tf32(float c[4], const uint32_t a[4], const uint32_t b[2]) {
    asm volatile("mma.sync.aligned.m16n8k8.row.col.f32.tf32.tf32.f32 "
        "{%0,%1,%2,%3}, {%4,%5,%6,%7}, {%8,%9}, {%0,%1,%2,%3};"
        : "+f"(c[0]), "+f"(c[1]), "+f"(c[2]), "+f"(c[3])
        : "r"(a[0]), "r"(a[1]), "r"(a[2]), "r"(a[3]), "r"(b[0]), "r"(b[1]));
}

// ---------------- tf32 HMMA projection GEMM --------------------------------
// C[m,n] = sum_k X[m,k]*W[n,k] + bias[n], scattered to g_q/g_k/g_v/g_pos.
// Block 256 thr (8 warps), tile 128x128, warp tile 32x64, K-chunk 32.
__global__ __launch_bounds__(256) void gemm_tc(
    const float* __restrict__ hs, const float* __restrict__ rel,
    const float* __restrict__ Wq, const float* __restrict__ bq,
    const float* __restrict__ Wk, const float* __restrict__ bk,
    const float* __restrict__ Wv, const float* __restrict__ bv,
    const float* __restrict__ Wpk, const float* __restrict__ bpk)
{
    __shared__ uint32_t As[128*36];
    __shared__ uint32_t Bs[128*36];

    const int which = blockIdx.z;
    if (which == 3 && blockIdx.y >= 8) return;

    const float* X    = (which == 3) ? rel : hs;
    const float* W    = (which == 0) ? Wq : (which == 1) ? Wk : (which == 2) ? Wv : Wpk;
    const float* bias = (which == 0) ? bq : (which == 1) ? bk : (which == 2) ? bv : bpk;
    float* outp       = (which == 0) ? g_q : (which == 1) ? g_k : (which == 2) ? g_v : g_pos;

    const int bm = blockIdx.y * 128;
    const int bn = blockIdx.x * 128;
    const int tid = threadIdx.x;
    const int wid = tid >> 5, lane = tid & 31;
    const int wm = wid >> 1, wn = wid & 1;         // warp grid 4x2
    const int g = lane >> 2, t = lane & 3;

    float acc[2][8][4];
#pragma unroll
    for (int mt = 0; mt < 2; mt++)
#pragma unroll
        for (int nt = 0; nt < 8; nt++)
#pragma unroll
            for (int i = 0; i < 4; i++) acc[mt][nt][i] = 0.f;

    const float* Ag = X + (size_t)bm * HIDN;
    const float* Bg = W + (size_t)bn * HIDN;

    for (int kc = 0; kc < 32; kc++) {
        float4 pa[4], pb[4];
#pragma unroll
        for (int i = 0; i < 4; i++) {
            const int fi = i * 256 + tid;
            const int row = fi >> 3, c4 = fi & 7;
            pa[i] = *(const float4*)(Ag + (size_t)row * HIDN + kc * 32 + c4 * 4);
            pb[i] = *(const float4*)(Bg + (size_t)row * HIDN + kc * 32 + c4 * 4);
        }
        __syncthreads();
#pragma unroll
        for (int i = 0; i < 4; i++) {
            const int fi = i * 256 + tid;
            const int row = fi >> 3, c4 = fi & 7;
            *(uint4*)&As[row*36 + c4*4] = make_uint4(f2tf(pa[i].x), f2tf(pa[i].y), f2tf(pa[i].z), f2tf(pa[i].w));
            *(uint4*)&Bs[row*36 + c4*4] = make_uint4(f2tf(pb[i].x), f2tf(pb[i].y), f2tf(pb[i].z), f2tf(pb[i].w));
        }
        __syncthreads();
#pragma unroll
        for (int ks = 0; ks < 4; ks++) {
            uint32_t a[2][4], b[8][2];
#pragma unroll
            for (int mt = 0; mt < 2; mt++) {
                const int ra = (wm*32 + mt*16 + g) * 36 + ks*8 + t;
                a[mt][0] = As[ra];
                a[mt][1] = As[ra + 8*36];
                a[mt][2] = As[ra + 4];
                a[mt][3] = As[ra + 8*36 + 4];
            }
#pragma unroll
            for (int nt = 0; nt < 8; nt++) {
                const int rb = (wn*64 + nt*8 + g) * 36 + ks*8 + t;
                b[nt][0] = Bs[rb];
                b[nt][1] = Bs[rb + 4];
            }
#pragma unroll
            for (int mt = 0; mt < 2; mt++)
#pragma unroll
                for (int nt = 0; nt < 8; nt++)
                    mma_tf32(acc[mt][nt], a[mt], b[nt]);
        }
    }

    // epilogue: C frag (c0,c1)=(row, col 2t..2t+1), (c2,c3)=(row+8, ...)
#pragma unroll
    for (int mt = 0; mt < 2; mt++) {
#pragma unroll
        for (int nt = 0; nt < 8; nt++) {
            const int n = bn + wn*64 + nt*8 + 2*t;
            const float bv0 = bias[n], bv1 = bias[n+1];
#pragma unroll
            for (int half = 0; half < 2; half++) {
                const int m = bm + wm*32 + mt*16 + g + half*8;
                const float v0 = acc[mt][nt][half*2+0] + bv0;
                const float v1 = acc[mt][nt][half*2+1] + bv1;
                size_t oi;
                if (which < 3) {
                    const int b_ = m >> 9, s = m & 511, h = n >> 6, d = n & 63;
                    oi = (((size_t)(b_*HH + h))*SS + s)*DD + d;
                } else {
                    oi = (((size_t)(n >> 6))*1024 + m)*DD + (n & 63);
                }
                *(float2*)(outp + oi) = make_float2(v0, v1);
            }
        }
    }
}

// ---------------- tf32 HMMA disentangled score kernel ----------------------
// Per 64x64 (i,j) tile: CC=Q@K^T (64x64), CPF=Q@P^T (64x128), PCF=P@K^T (128x64)
// over the 127-row pos band; diagonal scatter into SMEM S; write scores.
// 320 threads = 10 warps, each one 32x64 chunk.
__global__ __launch_bounds__(320) void score_tc(const float* __restrict__ mask)
{
    extern __shared__ uint32_t smw[];
    uint32_t* Qs = smw;                  // 64 x 68
    uint32_t* Ks = smw + 64*68;          // 64 x 68
    uint32_t* Ps = smw + 2*64*68;        // 128 x 68
    float*    Ss = (float*)(smw + 2*64*68 + 128*68);  // 64 x 65

    const int j0 = blockIdx.x * 64;
    const int i0 = blockIdx.y * 64;
    const int bh = blockIdx.z;
    const int b_ = bh >> 4, h = bh & 15;
    const int tid = threadIdx.x;
    const int wid = tid >> 5, lane = tid & 31;
    const int g = lane >> 2, t = lane & 3;

    const float* qptr = g_q + ((size_t)bh*SS + i0) * DD;
    const float* kptr = g_k + ((size_t)bh*SS + j0) * DD;
    const float* pptr = g_pos + (size_t)h * 1024 * DD;
    const int base = i0 - j0 + 449;

    // load tiles (cvt.rna to tf32 bits)
    for (int u = tid; u < 1024; u += 320) {
        const int row = u >> 4, c4 = u & 15;
        float4 qv = *(const float4*)(qptr + (size_t)row * DD + c4*4);
        float4 kv = *(const float4*)(kptr + (size_t)row * DD + c4*4);
        *(uint4*)&Qs[row*68 + c4*4] = make_uint4(f2tf(qv.x), f2tf(qv.y), f2tf(qv.z), f2tf(qv.w));
        *(uint4*)&Ks[row*68 + c4*4] = make_uint4(f2tf(kv.x), f2tf(kv.y), f2tf(kv.z), f2tf(kv.w));
    }
    for (int u = tid; u < 2048; u += 320) {
        const int r = u >> 4, c4 = u & 15;
        int grow = base + r;
        grow = grow < 0 ? 0 : (grow > 1023 ? 1023 : grow);
        float4 pv = *(const float4*)(pptr + (size_t)grow * DD + c4*4);
        *(uint4*)&Ps[r*68 + c4*4] = make_uint4(f2tf(pv.x), f2tf(pv.y), f2tf(pv.z), f2tf(pv.w));
    }
    __syncthreads();

    // warp chunk assignment
    const uint32_t* Ap; const uint32_t* Bp;
    int Arow, Brow;
    if (wid < 2)      { Ap = Qs; Arow = wid*32;          Bp = Ks; Brow = 0; }
    else if (wid < 6) { Ap = Qs; Arow = ((wid-2)&1)*32;  Bp = Ps; Brow = ((wid-2)>>1)*64; }
    else              { Ap = Ps; Arow = (wid-6)*32;      Bp = Ks; Brow = 0; }

    float acc[2][8][4];
#pragma unroll
    for (int mt = 0; mt < 2; mt++)
#pragma unroll
        for (int nt = 0; nt < 8; nt++)
#pragma unroll
            for (int i = 0; i < 4; i++) acc[mt][nt][i] = 0.f;

#pragma unroll
    for (int ks = 0; ks < 8; ks++) {
        uint32_t a[2][4], b[8][2];
#pragma unroll
        for (int mt = 0; mt < 2; mt++) {
            const int ra = (Arow + mt*16 + g) * 68 + ks*8 + t;
            a[mt][0] = Ap[ra];
            a[mt][1] = Ap[ra + 8*68];
            a[mt][2] = Ap[ra + 4];
            a[mt][3] = Ap[ra + 8*68 + 4];
        }
#pragma unroll
        for (int nt = 0; nt < 8; nt++) {
            const int rb = (Brow + nt*8 + g) * 68 + ks*8 + t;
            b[nt][0] = Bp[rb];
            b[nt][1] = Bp[rb + 4];
        }
#pragma unroll
        for (int mt = 0; mt < 2; mt++)
#pragma unroll
            for (int nt = 0; nt < 8; nt++)
                mma_tf32(acc[mt][nt], a[mt], b[nt]);
    }

    // ---- epilogue: CC writes, then CPF / PCF diagonal scatter-adds ----
    if (wid < 2) {
#pragma unroll
        for (int mt = 0; mt < 2; mt++)
#pragma unroll
            for (int nt = 0; nt < 8; nt++) {
                const int r0 = Arow + mt*16 + g;
                const int c0 = nt*8 + 2*t;
                Ss[r0*65 + c0]       = acc[mt][nt][0];
                Ss[r0*65 + c0 + 1]   = acc[mt][nt][1];
                Ss[(r0+8)*65 + c0]   = acc[mt][nt][2];
                Ss[(r0+8)*65 + c0+1] = acc[mt][nt][3];
            }
    }
    __syncthreads();
    if (wid >= 2 && wid < 6) {   // CPF[ai][p] -> S[ai][ai-p+63] * 0.125
#pragma unroll
        for (int mt = 0; mt < 2; mt++)
#pragma unroll
            for (int nt = 0; nt < 8; nt++) {
                const int ai0 = Arow + mt*16 + g;
                const int p0 = Brow + nt*8 + 2*t;
#pragma unroll
                for (int e = 0; e < 4; e++) {
                    const int ai = ai0 + (e >> 1)*8;
                    const int p  = p0 + (e & 1);
                    const int cj = ai - p + 63;
                    if ((unsigned)cj < 64u)
                        Ss[ai*65 + cj] += 0.125f * acc[mt][nt][e];
                }
            }
    }
    __syncthreads();
    if (wid >= 6) {              // PCF[r][cj] -> S[r+cj-63][cj]
#pragma unroll
        for (int mt = 0; mt < 2; mt++)
#pragma unroll
            for (int nt = 0; nt < 8; nt++) {
                const int r0 = Arow + mt*16 + g;
                const int c0 = nt*8 + 2*t;
#pragma unroll
                for (int e = 0; e < 4; e++) {
                    const int r  = r0 + (e >> 1)*8;
                    const int cj = c0 + (e & 1);
                    const int ai = r + cj - 63;
                    if ((unsigned)ai < 64u)
                        Ss[ai*65 + cj] += acc[mt][nt][e];
                }
            }
    }
    __syncthreads();

    const float s1 = 0.14433756729740643f;   // 1/sqrt(48)
    float* sp = g_scores + ((size_t)bh*SS + i0)*SS + j0;
    const float* mrow = mask + (size_t)b_*SS + j0;
    for (int u = tid; u < 4096; u += 320) {
        const int ai = u >> 6, cj = u & 63;
        sp[(size_t)ai*SS + cj] = Ss[ai*65 + cj] * s1 + mrow[cj];
    }
}

// ---------------- softmax stats --------------------------------------------
__global__ __launch_bounds__(256) void stats_kernel()
{
    const int warp = threadIdx.x >> 5;
    const int lane = threadIdx.x & 31;
    const size_t row = (size_t)blockIdx.x * 8 + warp;
    const float* sp = g_scores + row * SS;
    float v[16];
    float m = -1e30f;
#pragma unroll
    for (int t = 0; t < 4; t++) {
        float4 x = *(const float4*)(sp + t*128 + lane*4);
        v[t*4+0]=x.x; v[t*4+1]=x.y; v[t*4+2]=x.z; v[t*4+3]=x.w;
        m = fmaxf(m, fmaxf(fmaxf(x.x, x.y), fmaxf(x.z, x.w)));
    }
#pragma unroll
    for (int o = 16; o; o >>= 1) m = fmaxf(m, __shfl_xor_sync(0xffffffffu, m, o));
    float l = 0.f;
#pragma unroll
    for (int t = 0; t < 16; t++) l += __expf(v[t] - m);
#pragma unroll
    for (int o = 16; o; o >>= 1) l += __shfl_xor_sync(0xffffffffu, l, o);
    if (lane == 0) { g_m[row] = m; g_l[row] = l; }
}

// ---------------- PV --------------------------------------------------------
__global__ __launch_bounds__(256) void pv_kernel(float* __restrict__ out)
{
    __shared__ float psm[64][65];
    __shared__ float vs[64][65];
    __shared__ float mrow[64], lrow[64];
    const int i0 = blockIdx.y * 64;
    const int bh = blockIdx.z;
    const int b = bh >> 4, h = bh & 15;
    const int tid = threadIdx.x;
    const int tx = tid & 15, ty = tid >> 4;

    if (tid < 64) {
        mrow[tid] = g_m[(size_t)bh*SS + i0 + tid];
        lrow[tid] = 1.f / g_l[(size_t)bh*SS + i0 + tid];
    }
    __syncthreads();

    float acc[4][4];
#pragma unroll
    for (int a = 0; a < 4; a++)
#pragma unroll
        for (int c2 = 0; c2 < 4; c2++) acc[a][c2] = 0.f;

    const int r = tid >> 2;
    const int c = (tid & 3) << 4;
    const float m_r  = mrow[r];
    const float li_r = lrow[r];
    const float* srow = g_scores + ((size_t)bh*SS + i0 + r) * SS;

    for (int jc = 0; jc < SS; jc += 64) {
        __syncthreads();
#pragma unroll
        for (int u = 0; u < 16; u += 4) {
            float4 x = *(const float4*)(srow + jc + c + u);
            psm[r][c+u+0] = __expf(x.x - m_r) * li_r;
            psm[r][c+u+1] = __expf(x.y - m_r) * li_r;
            psm[r][c+u+2] = __expf(x.z - m_r) * li_r;
            psm[r][c+u+3] = __expf(x.w - m_r) * li_r;
        }
        const float* vrow = g_v + ((size_t)bh*SS + jc + r) * DD;
#pragma unroll
        for (int u = 0; u < 16; u += 4) {
            float4 x = *(const float4*)(vrow + c + u);
            vs[r][c+u+0]=x.x; vs[r][c+u+1]=x.y; vs[r][c+u+2]=x.z; vs[r][c+u+3]=x.w;
        }
        __syncthreads();
#pragma unroll 8
        for (int jj = 0; jj < 64; jj++) {
            float pf[4], vf[4];
#pragma unroll
            for (int a = 0; a < 4; a++) pf[a] = psm[ty*4+a][jj];
#pragma unroll
            for (int c2 = 0; c2 < 4; c2++) vf[c2] = vs[jj][tx*4+c2];
#pragma unroll
            for (int a = 0; a < 4; a++)
#pragma unroll
                for (int c2 = 0; c2 < 4; c2++) acc[a][c2] += pf[a] * vf[c2];
        }
    }

#pragma unroll
    for (int a = 0; a < 4; a++) {
        const int i = i0 + ty*4 + a;
#pragma unroll
        for (int c2 = 0; c2 < 4; c2++)
            out[((size_t)b*SS + i)*HIDN + h*DD + tx*4 + c2] = acc[a][c2];
    }
}

// ---------------- launch ---------------------------------------------------
extern "C" void kernel_launch(void* const* d_in, const int* in_sizes, int n_in,
                              void* d_out, int out_size)
{
    const float* hs  = (const float*)d_in[0];
    const float* msk = (const float*)d_in[1];
    const float* Wq  = (const float*)d_in[3];
    const float* bq  = (const float*)d_in[4];
    const float* Wk  = (const float*)d_in[5];
    const float* bk  = (const float*)d_in[6];
    const float* Wv  = (const float*)d_in[7];
    const float* bv  = (const float*)d_in[8];
    const float* Wpk = (const float*)d_in[9];
    const float* bpk = (const float*)d_in[10];
    const float* rel = (const float*)d_in[11];
    float* out = (float*)d_out;

    const int score_smem = (2*64*68 + 128*68) * 4 + 64*65*4;  // 86272 B
    static int configured = 0;
    if (!configured) {
        cudaFuncSetAttribute(score_tc, cudaFuncAttributeMaxDynamicSharedMemorySize, score_smem);
        configured = 1;
    }

    dim3 gg(8, 32, 4);                    // z: Wq, Wk, Wv, Wpk (y>=8 idles for z=3)
    gemm_tc<<<gg, 256>>>(hs, rel, Wq, bq, Wk, bk, Wv, bv, Wpk, bpk);

    dim3 gs(SS/64, SS/64, BH);            // (8, 8, 128)
    score_tc<<<gs, 320, score_smem>>>(msk);

    stats_kernel<<<BH*SS/8, 256>>>();

    dim3 gpv(1, SS/64, BH);               // (1, 8, 128)
    pv_kernel<<<gpv, 256>>>(out);
}

// round 4
// speedup vs baseline: 1.7695x; 1.1597x over previous
#include <cuda_runtime.h>
#include <cstdint>

#define BB   8
#define SS   512
#define HH   16
#define DD   64
#define HIDN 1024
#define BH   (BB*HH)   // 128

// ---------------- scratch (device globals: allocation-free) ----------------
__device__ float g_q[BH*SS*DD];                 // [b,h,s,d] 16MB
__device__ float g_k[BH*SS*DD];
__device__ float g_v[BH*SS*DD];
__device__ float g_pos[HH*1024*DD];             // [h,p,d]   4MB

// ---------------- helpers ---------------------------------------------------
__device__ __forceinline__ uint32_t f2tf(float f) {
    uint32_t u;
    asm("cvt.rna.tf32.f32 %0, %1;" : "=r"(u) : "f"(f));
    return u;
}
__device__ __forceinline__ void mma_tf32(float c[4], const uint32_t a[4], const uint32_t b[2]) {
    asm volatile("mma.sync.aligned.m16n8k8.row.col.f32.tf32.tf32.f32 "
        "{%0,%1,%2,%3}, {%4,%5,%6,%7}, {%8,%9}, {%0,%1,%2,%3};"
        : "+f"(c[0]), "+f"(c[1]), "+f"(c[2]), "+f"(c[3])
        : "r"(a[0]), "r"(a[1]), "r"(a[2]), "r"(a[3]), "r"(b[0]), "r"(b[1]));
}

// ---------------- tf32 HMMA projection GEMM (unchanged from R3) ------------
__global__ __launch_bounds__(256) void gemm_tc(
    const float* __restrict__ hs, const float* __restrict__ rel,
    const float* __restrict__ Wq, const float* __restrict__ bq,
    const float* __restrict__ Wk, const float* __restrict__ bk,
    const float* __restrict__ Wv, const float* __restrict__ bv,
    const float* __restrict__ Wpk, const float* __restrict__ bpk)
{
    __shared__ uint32_t As[128*36];
    __shared__ uint32_t Bs[128*36];

    const int which = blockIdx.z;
    if (which == 3 && blockIdx.y >= 8) return;

    const float* X    = (which == 3) ? rel : hs;
    const float* W    = (which == 0) ? Wq : (which == 1) ? Wk : (which == 2) ? Wv : Wpk;
    const float* bias = (which == 0) ? bq : (which == 1) ? bk : (which == 2) ? bv : bpk;
    float* outp       = (which == 0) ? g_q : (which == 1) ? g_k : (which == 2) ? g_v : g_pos;

    const int bm = blockIdx.y * 128;
    const int bn = blockIdx.x * 128;
    const int tid = threadIdx.x;
    const int wid = tid >> 5, lane = tid & 31;
    const int wm = wid >> 1, wn = wid & 1;
    const int g = lane >> 2, t = lane & 3;

    float acc[2][8][4];
#pragma unroll
    for (int mt = 0; mt < 2; mt++)
#pragma unroll
        for (int nt = 0; nt < 8; nt++)
#pragma unroll
            for (int i = 0; i < 4; i++) acc[mt][nt][i] = 0.f;

    const float* Ag = X + (size_t)bm * HIDN;
    const float* Bg = W + (size_t)bn * HIDN;

    for (int kc = 0; kc < 32; kc++) {
        float4 pa[4], pb[4];
#pragma unroll
        for (int i = 0; i < 4; i++) {
            const int fi = i * 256 + tid;
            const int row = fi >> 3, c4 = fi & 7;
            pa[i] = *(const float4*)(Ag + (size_t)row * HIDN + kc * 32 + c4 * 4);
            pb[i] = *(const float4*)(Bg + (size_t)row * HIDN + kc * 32 + c4 * 4);
        }
        __syncthreads();
#pragma unroll
        for (int i = 0; i < 4; i++) {
            const int fi = i * 256 + tid;
            const int row = fi >> 3, c4 = fi & 7;
            *(uint4*)&As[row*36 + c4*4] = make_uint4(f2tf(pa[i].x), f2tf(pa[i].y), f2tf(pa[i].z), f2tf(pa[i].w));
            *(uint4*)&Bs[row*36 + c4*4] = make_uint4(f2tf(pb[i].x), f2tf(pb[i].y), f2tf(pb[i].z), f2tf(pb[i].w));
        }
        __syncthreads();
#pragma unroll
        for (int ks = 0; ks < 4; ks++) {
            uint32_t a[2][4], b[8][2];
#pragma unroll
            for (int mt = 0; mt < 2; mt++) {
                const int ra = (wm*32 + mt*16 + g) * 36 + ks*8 + t;
                a[mt][0] = As[ra];
                a[mt][1] = As[ra + 8*36];
                a[mt][2] = As[ra + 4];
                a[mt][3] = As[ra + 8*36 + 4];
            }
#pragma unroll
            for (int nt = 0; nt < 8; nt++) {
                const int rb = (wn*64 + nt*8 + g) * 36 + ks*8 + t;
                b[nt][0] = Bs[rb];
                b[nt][1] = Bs[rb + 4];
            }
#pragma unroll
            for (int mt = 0; mt < 2; mt++)
#pragma unroll
                for (int nt = 0; nt < 8; nt++)
                    mma_tf32(acc[mt][nt], a[mt], b[nt]);
        }
    }

#pragma unroll
    for (int mt = 0; mt < 2; mt++) {
#pragma unroll
        for (int nt = 0; nt < 8; nt++) {
            const int n = bn + wn*64 + nt*8 + 2*t;
            const float bv0 = bias[n], bv1 = bias[n+1];
#pragma unroll
            for (int half = 0; half < 2; half++) {
                const int m = bm + wm*32 + mt*16 + g + half*8;
                const float v0 = acc[mt][nt][half*2+0] + bv0;
                const float v1 = acc[mt][nt][half*2+1] + bv1;
                size_t oi;
                if (which < 3) {
                    const int b_ = m >> 9, s = m & 511, h = n >> 6, d = n & 63;
                    oi = (((size_t)(b_*HH + h))*SS + s)*DD + d;
                } else {
                    oi = (((size_t)(n >> 6))*1024 + m)*DD + (n & 63);
                }
                *(float2*)(outp + oi) = make_float2(v0, v1);
            }
        }
    }
}

// ---------------- fused flash kernel: scores + softmax + PV ----------------
// Per CTA: i-tile (64 rows) x one (b,h). Loop 8 j-chunks of 64:
//   score tile via 3 HMMA chunks + diagonal scatter (as R3 score_tc),
//   online softmax, P~ @ V^T accumulate via HMMA. Never materializes scores.
// 320 threads = 10 warps.
#define FL_SMEM ((4352*5 + 8704 + 4160 + 256) * 4)   // 122112 B

__global__ __launch_bounds__(320) void flash_tc(const float* __restrict__ mask,
                                                float* __restrict__ out)
{
    extern __shared__ uint32_t smw[];
    uint32_t* Qs = smw;                    // 64 x 68
    uint32_t* Ks = Qs + 4352;              // 64 x 68
    uint32_t* Ps = Ks + 4352;              // 128 x 68 (pos band)
    uint32_t* Pt = Ps + 8704;              // 64 x 68 (P~ tf32)
    uint32_t* Vt = Pt + 4352;              // 64 x 68 (V transposed: [d][j])
    float*    Ss = (float*)(Vt + 4352);    // 64 x 65 (raw score accum)
    float* sm_m     = Ss + 4160;
    float* sm_l     = sm_m + 64;
    float* sm_scale = sm_l + 64;
    float* sm_mask  = sm_scale + 64;

    const int i0 = blockIdx.x * 64;
    const int bh = blockIdx.y;
    const int b_ = bh >> 4, h = bh & 15;
    const int tid = threadIdx.x;
    const int wid = tid >> 5, lane = tid & 31;
    const int g = lane >> 2, t = lane & 3;
    const int wm = wid >> 1, wn = wid & 1;      // PV warp grid (wid<8): 4x2

    const float* qptr = g_q + ((size_t)bh*SS + i0) * DD;
    const float* kbase = g_k + (size_t)bh*SS*DD;
    const float* vbase = g_v + (size_t)bh*SS*DD;
    const float* pptr = g_pos + (size_t)h * 1024 * DD;

    // Q tile once
    for (int u = tid; u < 1024; u += 320) {
        const int row = u >> 4, c4 = u & 15;
        float4 qv = *(const float4*)(qptr + (size_t)row * DD + c4*4);
        *(uint4*)&Qs[row*68 + c4*4] = make_uint4(f2tf(qv.x), f2tf(qv.y), f2tf(qv.z), f2tf(qv.w));
    }
    if (tid < 64) { sm_m[tid] = -1e30f; sm_l[tid] = 0.f; }

    float acc_o[4][4];                          // PV out accum (wid<8)
#pragma unroll
    for (int nt = 0; nt < 4; nt++)
#pragma unroll
        for (int e = 0; e < 4; e++) acc_o[nt][e] = 0.f;

    // score-phase chunk assignment (identical to R3 score_tc)
    const uint32_t* Ap; const uint32_t* Bp;
    int Arow, Brow;
    if (wid < 2)      { Ap = Qs; Arow = wid*32;          Bp = Ks; Brow = 0; }
    else if (wid < 6) { Ap = Qs; Arow = ((wid-2)&1)*32;  Bp = Ps; Brow = ((wid-2)>>1)*64; }
    else              { Ap = Ps; Arow = (wid-6)*32;      Bp = Ks; Brow = 0; }

    const float s1 = 0.14433756729740643f;      // 1/sqrt(48)

    for (int j0 = 0; j0 < SS; j0 += 64) {
        __syncthreads();   // previous chunk's Pt/Vt/Ks/Ps reads complete
        // ---- loads: K chunk, V chunk (transposed), pos band, mask row ----
        for (int u = tid; u < 1024; u += 320) {
            const int row = u >> 4, c4 = u & 15;
            float4 kv = *(const float4*)(kbase + (size_t)(j0+row) * DD + c4*4);
            *(uint4*)&Ks[row*68 + c4*4] = make_uint4(f2tf(kv.x), f2tf(kv.y), f2tf(kv.z), f2tf(kv.w));
            float4 vv = *(const float4*)(vbase + (size_t)(j0+row) * DD + c4*4);
            uint32_t ve[4] = {f2tf(vv.x), f2tf(vv.y), f2tf(vv.z), f2tf(vv.w)};
#pragma unroll
            for (int e2 = 0; e2 < 4; e2++) {    // e-rotation breaks STS conflicts
                const int e = (e2 + c4) & 3;
                Vt[(c4*4 + e)*68 + row] = ve[e];
            }
        }
        const int base = i0 - j0 + 449;
        for (int u = tid; u < 2048; u += 320) {
            const int r = u >> 4, c4 = u & 15;
            int grow = base + r;
            grow = grow < 0 ? 0 : (grow > 1023 ? 1023 : grow);
            float4 pv = *(const float4*)(pptr + (size_t)grow * DD + c4*4);
            *(uint4*)&Ps[r*68 + c4*4] = make_uint4(f2tf(pv.x), f2tf(pv.y), f2tf(pv.z), f2tf(pv.w));
        }
        if (tid < 64) sm_mask[tid] = mask[(size_t)b_*SS + j0 + tid];
        __syncthreads();

        // ---- score MMAs ----
        float acc[2][8][4];
#pragma unroll
        for (int mt = 0; mt < 2; mt++)
#pragma unroll
            for (int nt = 0; nt < 8; nt++)
#pragma unroll
                for (int e = 0; e < 4; e++) acc[mt][nt][e] = 0.f;

#pragma unroll
        for (int ks = 0; ks < 8; ks++) {
            uint32_t a[2][4], b[8][2];
#pragma unroll
            for (int mt = 0; mt < 2; mt++) {
                const int ra = (Arow + mt*16 + g) * 68 + ks*8 + t;
                a[mt][0] = Ap[ra];
                a[mt][1] = Ap[ra + 8*68];
                a[mt][2] = Ap[ra + 4];
                a[mt][3] = Ap[ra + 8*68 + 4];
            }
#pragma unroll
            for (int nt = 0; nt < 8; nt++) {
                const int rb = (Brow + nt*8 + g) * 68 + ks*8 + t;
                b[nt][0] = Bp[rb];
                b[nt][1] = Bp[rb + 4];
            }
#pragma unroll
            for (int mt = 0; mt < 2; mt++)
#pragma unroll
                for (int nt = 0; nt < 8; nt++)
                    mma_tf32(acc[mt][nt], a[mt], b[nt]);
        }

        // ---- epilogue: CC writes, then CPF / PCF diagonal scatter-adds ----
        if (wid < 2) {
#pragma unroll
            for (int mt = 0; mt < 2; mt++)
#pragma unroll
                for (int nt = 0; nt < 8; nt++) {
                    const int r0 = Arow + mt*16 + g;
                    const int c0 = nt*8 + 2*t;
                    Ss[r0*65 + c0]       = acc[mt][nt][0];
                    Ss[r0*65 + c0 + 1]   = acc[mt][nt][1];
                    Ss[(r0+8)*65 + c0]   = acc[mt][nt][2];
                    Ss[(r0+8)*65 + c0+1] = acc[mt][nt][3];
                }
        }
        __syncthreads();
        if (wid >= 2 && wid < 6) {   // CPF[ai][p] -> S[ai][ai-p+63] * 0.125
#pragma unroll
            for (int mt = 0; mt < 2; mt++)
#pragma unroll
                for (int nt = 0; nt < 8; nt++) {
                    const int ai0 = Arow + mt*16 + g;
                    const int p0 = Brow + nt*8 + 2*t;
#pragma unroll
                    for (int e = 0; e < 4; e++) {
                        const int ai = ai0 + (e >> 1)*8;
                        const int p  = p0 + (e & 1);
                        const int cj = ai - p + 63;
                        if ((unsigned)cj < 64u)
                            Ss[ai*65 + cj] += 0.125f * acc[mt][nt][e];
                    }
                }
        }
        __syncthreads();
        if (wid >= 6) {              // PCF[r][cj] -> S[r+cj-63][cj]
#pragma unroll
            for (int mt = 0; mt < 2; mt++)
#pragma unroll
                for (int nt = 0; nt < 8; nt++) {
                    const int r0 = Arow + mt*16 + g;
                    const int c0 = nt*8 + 2*t;
#pragma unroll
                    for (int e = 0; e < 4; e++) {
                        const int r  = r0 + (e >> 1)*8;
                        const int cj = c0 + (e & 1);
                        const int ai = r + cj - 63;
                        if ((unsigned)ai < 64u)
                            Ss[ai*65 + cj] += acc[mt][nt][e];
                    }
                }
        }
        __syncthreads();

        // ---- online softmax: threads 0..255, 4 threads per row ----
        if (tid < 256) {
            const int row = tid >> 2, q4 = tid & 3;
            float mloc = -1e30f;
#pragma unroll
            for (int c = q4*16; c < q4*16 + 16; c++) {
                const float val = Ss[row*65 + c] * s1 + sm_mask[c];
                Ss[row*65 + c] = val;
                mloc = fmaxf(mloc, val);
            }
            mloc = fmaxf(mloc, __shfl_xor_sync(0xffffffffu, mloc, 1));
            mloc = fmaxf(mloc, __shfl_xor_sync(0xffffffffu, mloc, 2));
            const float mold = sm_m[row];
            const float mnew = fmaxf(mold, mloc);
            float lsum = 0.f;
#pragma unroll
            for (int c = q4*16; c < q4*16 + 16; c++) {
                const float p = __expf(Ss[row*65 + c] - mnew);
                Pt[row*68 + c] = f2tf(p);
                lsum += p;
            }
            lsum += __shfl_xor_sync(0xffffffffu, lsum, 1);
            lsum += __shfl_xor_sync(0xffffffffu, lsum, 2);
            if (q4 == 0) {
                const float sc = __expf(mold - mnew);
                sm_m[row] = mnew;
                sm_scale[row] = sc;
                sm_l[row] = sm_l[row] * sc + lsum;
            }
        }
        __syncthreads();

        // ---- PV: warps 0..7, out tile 64x64, warp tile 16x32 ----
        if (wid < 8) {
            const float sc0 = sm_scale[wm*16 + g];
            const float sc1 = sm_scale[wm*16 + g + 8];
#pragma unroll
            for (int nt = 0; nt < 4; nt++) {
                acc_o[nt][0] *= sc0; acc_o[nt][1] *= sc0;
                acc_o[nt][2] *= sc1; acc_o[nt][3] *= sc1;
            }
#pragma unroll
            for (int ks = 0; ks < 8; ks++) {
                uint32_t a[4], b[4][2];
                const int ra = (wm*16 + g) * 68 + ks*8 + t;
                a[0] = Pt[ra];
                a[1] = Pt[ra + 8*68];
                a[2] = Pt[ra + 4];
                a[3] = Pt[ra + 8*68 + 4];
#pragma unroll
                for (int nt = 0; nt < 4; nt++) {
                    const int rb = (wn*32 + nt*8 + g) * 68 + ks*8 + t;
                    b[nt][0] = Vt[rb];
                    b[nt][1] = Vt[rb + 4];
                }
#pragma unroll
                for (int nt = 0; nt < 4; nt++)
                    mma_tf32(acc_o[nt], a, b[nt]);
            }
        }
    }
    __syncthreads();

    // ---- finalize: out[i][d] = acc_o / l ----
    if (wid < 8) {
        const int r0 = wm*16 + g;
        const float inv0 = 1.f / sm_l[r0];
        const float inv1 = 1.f / sm_l[r0 + 8];
#pragma unroll
        for (int nt = 0; nt < 4; nt++) {
            const int col = wn*32 + nt*8 + 2*t;
            const size_t o0 = ((size_t)b_*SS + i0 + r0)*HIDN + h*DD + col;
            const size_t o1 = ((size_t)b_*SS + i0 + r0 + 8)*HIDN + h*DD + col;
            *(float2*)(out + o0) = make_float2(acc_o[nt][0]*inv0, acc_o[nt][1]*inv0);
            *(float2*)(out + o1) = make_float2(acc_o[nt][2]*inv1, acc_o[nt][3]*inv1);
        }
    }
}

// ---------------- launch ---------------------------------------------------
extern "C" void kernel_launch(void* const* d_in, const int* in_sizes, int n_in,
                              void* d_out, int out_size)
{
    const float* hs  = (const float*)d_in[0];
    const float* msk = (const float*)d_in[1];
    const float* Wq  = (const float*)d_in[3];
    const float* bq  = (const float*)d_in[4];
    const float* Wk  = (const float*)d_in[5];
    const float* bk  = (const float*)d_in[6];
    const float* Wv  = (const float*)d_in[7];
    const float* bv  = (const float*)d_in[8];
    const float* Wpk = (const float*)d_in[9];
    const float* bpk = (const float*)d_in[10];
    const float* rel = (const float*)d_in[11];
    float* out = (float*)d_out;

    cudaFuncSetAttribute(flash_tc, cudaFuncAttributeMaxDynamicSharedMemorySize, FL_SMEM);

    dim3 gg(8, 32, 4);                    // z: Wq, Wk, Wv, Wpk (y>=8 idles for z=3)
    gemm_tc<<<gg, 256>>>(hs, rel, Wq, bq, Wk, bk, Wv, bv, Wpk, bpk);

    dim3 gf(SS/64, BH);                   // (8, 128)
    flash_tc<<<gf, 320, FL_SMEM>>>(msk, out);
}